// round 1
// baseline (speedup 1.0000x reference)
#include <cuda_runtime.h>
#include <cstdint>

// ---------------- problem constants ----------------
#define BATCH 16
#define TT    100          // channels == time steps
#define W_IN  132
#define H1    159
#define H2    150          // after conv1
#define H3    141          // after conv2
#define H4    132          // after conv3
#define FEAT  (H4*W_IN)    // 17424
#define HID   100
#define NC    14
#define NL    3

#define N1 (H2*W_IN)   // 19800
#define N2 (H3*W_IN)   // 18612
#define N3 (H4*W_IN)   // 17424

// ---------------- scratch (static device globals; no allocs) ----------------
__device__ float g_c1[(size_t)BATCH*TT*N1];
__device__ float g_c2[(size_t)BATCH*TT*N2];
__device__ float g_c3[(size_t)BATCH*TT*N3];
__device__ float g_xw[(size_t)BATCH*TT*3*HID];
__device__ float g_wt[3*1000*128];   // transposed padded conv weights: [conv][i*10+kh][o(128)]

// ---------------- f32x2 helpers (FFMA2) ----------------
__device__ __forceinline__ unsigned long long pack2(float lo, float hi) {
    unsigned long long r;
    asm("mov.b64 %0, {%1, %2};" : "=l"(r) : "r"(__float_as_uint(lo)), "r"(__float_as_uint(hi)));
    return r;
}
__device__ __forceinline__ void fma2(unsigned long long& d, unsigned long long a, unsigned long long b) {
    asm("fma.rn.f32x2 %0, %1, %2, %0;" : "+l"(d) : "l"(a), "l"(b));
}
__device__ __forceinline__ void unpack2(unsigned long long v, float& lo, float& hi) {
    unsigned int a, b;
    asm("mov.b64 {%0, %1}, %2;" : "=r"(a), "=r"(b) : "l"(v));
    lo = __uint_as_float(a); hi = __uint_as_float(b);
}

// ---------------- weight transpose/pad prep ----------------
__global__ void prep_w_kernel(const float* __restrict__ w1, const float* __restrict__ w2,
                              const float* __restrict__ w3, float* __restrict__ wt) {
    int idx = blockIdx.x * 256 + threadIdx.x;        // over 3*1000*128
    if (idx >= 3 * 128000) return;
    int c   = idx / 128000;
    int rem = idx - c * 128000;
    int row = rem >> 7;          // i*10+kh
    int o   = rem & 127;
    int i   = row / 10, kh = row - i * 10;
    const float* w = (c == 0) ? w1 : (c == 1) ? w2 : w3;
    wt[idx] = (o < 100) ? w[(o * 100 + i) * 10 + kh] : 0.f;
}

// ---------------- conv as GEMM (implicit shifted-view im2col) ----------------
// X: [B,100,Hin,132]  Wt: [100*10 rows][128]  Y: [B,100,Hout,132]
// Y[b,o,n] = sum_{i,kh} Wt[(i*10+kh)][o] * X[b,i, n + 132*kh] + bias[o]
__global__ __launch_bounds__(256, 2)
void conv_kernel(const float* __restrict__ X, const float* __restrict__ Wt,
                 const float* __restrict__ bias, float* __restrict__ Y,
                 int Hin, int Nout) {
    const int plane = Hin * W_IN;
    const int b  = blockIdx.y;
    const int n0 = blockIdx.x * 128;
    __shared__ __align__(16) float xs[1320];
    __shared__ __align__(16) float ws[10][128];
    const int tid = threadIdx.x;
    const int tm = tid >> 4, tn = tid & 15;

    unsigned long long acc[8][4];
#pragma unroll
    for (int r = 0; r < 8; ++r)
#pragma unroll
        for (int p = 0; p < 4; ++p) acc[r][p] = 0ULL;

    const float* Xb = X + (size_t)b * 100 * plane;
    const int lim = plane - n0;   // number of valid xs entries from n0

    for (int i = 0; i < 100; ++i) {
        const float* xsrc = Xb + (size_t)i * plane + n0;
        for (int j = tid; j < 1316; j += 256)
            xs[j] = (j < lim) ? xsrc[j] : 0.f;
        const float4* wsrc = (const float4*)(Wt + i * 1280);
        for (int j = tid; j < 320; j += 256)
            ((float4*)ws)[j] = wsrc[j];
        __syncthreads();

#pragma unroll
        for (int kh = 0; kh < 10; ++kh) {
            float4 a0 = *(const float4*)&ws[kh][tm * 8];
            float4 a1 = *(const float4*)&ws[kh][tm * 8 + 4];
            const unsigned long long* bp =
                (const unsigned long long*)&xs[kh * 132 + tn * 8];
            unsigned long long bb0 = bp[0], bb1 = bp[1], bb2 = bp[2], bb3 = bp[3];
            float av[8] = {a0.x, a0.y, a0.z, a0.w, a1.x, a1.y, a1.z, a1.w};
#pragma unroll
            for (int r = 0; r < 8; ++r) {
                unsigned long long ar = pack2(av[r], av[r]);
                fma2(acc[r][0], ar, bb0);
                fma2(acc[r][1], ar, bb1);
                fma2(acc[r][2], ar, bb2);
                fma2(acc[r][3], ar, bb3);
            }
        }
        __syncthreads();
    }

#pragma unroll
    for (int r = 0; r < 8; ++r) {
        int o = tm * 8 + r;
        if (o < 100) {
            float bo = bias[o];
            float* yrow = Y + ((size_t)b * 100 + o) * Nout;
#pragma unroll
            for (int p = 0; p < 4; ++p) {
                float lo, hi;
                unpack2(acc[r][p], lo, hi);
                int n = n0 + tn * 8 + 2 * p;
                if (n     < Nout) yrow[n]     = lo + bo;
                if (n + 1 < Nout) yrow[n + 1] = hi + bo;
            }
        }
    }
}

// ---------------- GRU input GEMM: xw[bt,g] = gi[bt,:] . w_ih[g,:] + b_ih[g] ----------------
// gi = g_c3 viewed [1600][17424], w_ih [300][17424]. tiles 64x64, K-chunk 16, no split-K.
__global__ __launch_bounds__(256)
void gemm_xw_kernel(const float* __restrict__ gi, const float* __restrict__ wih,
                    const float* __restrict__ bih, float* __restrict__ xw) {
    const int bt0 = blockIdx.x * 64;
    const int g0  = blockIdx.y * 64;
    __shared__ __align__(16) float as[16][68];
    __shared__ __align__(16) float bs[16][68];
    const int tid = threadIdx.x;
    const int lm = tid >> 2, lk = (tid & 3) * 4;
    const int tm = tid >> 4, tn = tid & 15;

    float acc[4][4];
#pragma unroll
    for (int r = 0; r < 4; ++r)
#pragma unroll
        for (int c = 0; c < 4; ++c) acc[r][c] = 0.f;

    const float* arow = gi + (size_t)(bt0 + lm) * FEAT + lk;
    const bool bvalid = (g0 + lm) < 300;
    const float* brow = wih + (size_t)(bvalid ? (g0 + lm) : 0) * FEAT + lk;

    for (int ch = 0; ch < FEAT / 16; ++ch) {          // 1089 chunks
        float4 av = *(const float4*)arow;  arow += 16;
        float4 bv = bvalid ? *(const float4*)brow : make_float4(0.f, 0.f, 0.f, 0.f);
        brow += 16;
        as[lk + 0][lm] = av.x; as[lk + 1][lm] = av.y; as[lk + 2][lm] = av.z; as[lk + 3][lm] = av.w;
        bs[lk + 0][lm] = bv.x; bs[lk + 1][lm] = bv.y; bs[lk + 2][lm] = bv.z; bs[lk + 3][lm] = bv.w;
        __syncthreads();
#pragma unroll
        for (int k = 0; k < 16; ++k) {
            float4 a4 = *(const float4*)&as[k][tm * 4];
            float4 b4 = *(const float4*)&bs[k][tn * 4];
            float aa[4] = {a4.x, a4.y, a4.z, a4.w};
            float bb[4] = {b4.x, b4.y, b4.z, b4.w};
#pragma unroll
            for (int r = 0; r < 4; ++r)
#pragma unroll
                for (int c = 0; c < 4; ++c) acc[r][c] += aa[r] * bb[c];
        }
        __syncthreads();
    }
#pragma unroll
    for (int r = 0; r < 4; ++r) {
        int bt = bt0 + tm * 4 + r;
#pragma unroll
        for (int c = 0; c < 4; ++c) {
            int g = g0 + tn * 4 + c;
            if (g < 300) xw[(size_t)bt * 300 + g] = acc[r][c] + bih[g];
        }
    }
}

// ---------------- GRU recurrence + heads (one CTA per batch element) ----------------
__global__ __launch_bounds__(320, 1)
void gru_kernel(const float* __restrict__ xw, const float* __restrict__ whh,
                const float* __restrict__ bhh,
                const float* __restrict__ wy1, const float* __restrict__ by1,
                const float* __restrict__ wy2, const float* __restrict__ by2,
                float* __restrict__ out) {
    const int b = blockIdx.x;
    const int tid = threadIdx.x;
    __shared__ float h_s[HID];
    __shared__ float gh_s[3 * HID];
    __shared__ float wy_s[(NC + NL) * HID];
    __shared__ float by_s[NC + NL];

    for (int j = tid; j < NC * HID; j += 320) wy_s[j] = wy1[j];
    for (int j = tid; j < NL * HID; j += 320) wy_s[NC * HID + j] = wy2[j];
    if (tid < NC) by_s[tid] = by1[tid];
    else if (tid < NC + NL) by_s[tid] = by2[tid - NC];
    if (tid < HID) h_s[tid] = 0.f;

    float wreg[HID];
    float bh = 0.f;
    if (tid < 3 * HID) {
        const float4* wrow = (const float4*)(whh + (size_t)tid * HID);
#pragma unroll
        for (int j = 0; j < HID / 4; ++j) {
            float4 v = wrow[j];
            wreg[4 * j] = v.x; wreg[4 * j + 1] = v.y; wreg[4 * j + 2] = v.z; wreg[4 * j + 3] = v.w;
        }
        bh = bhh[tid];
    }
    __syncthreads();

    const float* xwb = xw + (size_t)b * TT * 3 * HID;
    float* y1o = out + (size_t)b * TT * NC;
    float* y2o = out + (size_t)BATCH * TT * NC + (size_t)b * TT * NL;

    for (int t = 0; t < TT; ++t) {
        const float* xwt = xwb + t * 3 * HID;
        if (tid < 3 * HID) {
            float s0 = 0.f, s1 = 0.f, s2 = 0.f, s3 = 0.f;
#pragma unroll
            for (int j = 0; j < HID; j += 4) {
                s0 += wreg[j]     * h_s[j];
                s1 += wreg[j + 1] * h_s[j + 1];
                s2 += wreg[j + 2] * h_s[j + 2];
                s3 += wreg[j + 3] * h_s[j + 3];
            }
            gh_s[tid] = bh + ((s0 + s1) + (s2 + s3));
        } else if (t > 0 && tid < 300 + NC + NL) {
            // heads for t-1, overlapped with gh compute (h_s still holds h_{t-1})
            int c = tid - 300;
            float s = by_s[c];
            const float* wr = &wy_s[c * HID];
#pragma unroll 4
            for (int j = 0; j < HID; ++j) s += wr[j] * h_s[j];
            if (c < NC) y1o[(t - 1) * NC + c] = 1.f / (1.f + expf(-s));
            else        y2o[(t - 1) * NL + (c - NC)] = tanhf(s) * 10.f;
        }
        __syncthreads();
        if (tid < HID) {
            float ghr = gh_s[tid], ghz = gh_s[HID + tid], ghn = gh_s[2 * HID + tid];
            float xr = xwt[tid], xz = xwt[HID + tid], xn = xwt[2 * HID + tid];
            float r = 1.f / (1.f + expf(-(xr + ghr)));
            float z = 1.f / (1.f + expf(-(xz + ghz)));
            float n = tanhf(xn + r * ghn);
            h_s[tid] = (1.f - z) * n + z * h_s[tid];
        }
        __syncthreads();
    }
    // heads for the final step t = TT-1
    if (tid >= 300 && tid < 300 + NC + NL) {
        int c = tid - 300;
        float s = by_s[c];
        const float* wr = &wy_s[c * HID];
#pragma unroll 4
        for (int j = 0; j < HID; ++j) s += wr[j] * h_s[j];
        if (c < NC) y1o[(TT - 1) * NC + c] = 1.f / (1.f + expf(-s));
        else        y2o[(TT - 1) * NL + (c - NC)] = tanhf(s) * 10.f;
    }
}

// ---------------- launch ----------------
extern "C" void kernel_launch(void* const* d_in, const int* in_sizes, int n_in,
                              void* d_out, int out_size) {
    const float* x    = (const float*)d_in[0];
    const float* w1   = (const float*)d_in[1];
    const float* bc1  = (const float*)d_in[2];
    const float* w2   = (const float*)d_in[3];
    const float* bc2  = (const float*)d_in[4];
    const float* w3   = (const float*)d_in[5];
    const float* bc3  = (const float*)d_in[6];
    const float* w_ih = (const float*)d_in[7];
    const float* w_hh = (const float*)d_in[8];
    const float* b_ih = (const float*)d_in[9];
    const float* b_hh = (const float*)d_in[10];
    const float* w_y1 = (const float*)d_in[11];
    const float* b_y1 = (const float*)d_in[12];
    const float* w_y2 = (const float*)d_in[13];
    const float* b_y2 = (const float*)d_in[14];

    float *c1, *c2, *c3, *xw, *wt;
    cudaGetSymbolAddress((void**)&c1, g_c1);
    cudaGetSymbolAddress((void**)&c2, g_c2);
    cudaGetSymbolAddress((void**)&c3, g_c3);
    cudaGetSymbolAddress((void**)&xw, g_xw);
    cudaGetSymbolAddress((void**)&wt, g_wt);

    prep_w_kernel<<<(3 * 128000 + 255) / 256, 256>>>(w1, w2, w3, wt);

    conv_kernel<<<dim3((N1 + 127) / 128, BATCH), 256>>>(x,  wt,          bc1, c1, H1, N1);
    conv_kernel<<<dim3((N2 + 127) / 128, BATCH), 256>>>(c1, wt + 128000, bc2, c2, H2, N2);
    conv_kernel<<<dim3((N3 + 127) / 128, BATCH), 256>>>(c2, wt + 256000, bc3, c3, H3, N3);

    gemm_xw_kernel<<<dim3(1600 / 64, (300 + 63) / 64), 256>>>(c3, w_ih, b_ih, xw);

    gru_kernel<<<BATCH, 320>>>(xw, w_hh, b_hh, w_y1, b_y1, w_y2, b_y2, (float*)d_out);
}

// round 2
// speedup vs baseline: 1.9506x; 1.9506x over previous
#include <cuda_runtime.h>
#include <cstdint>

typedef unsigned long long ull;

// ---------------- problem constants ----------------
#define BATCH 16
#define TT    100
#define W_IN  132
#define H1    159
#define H4    132
#define PLANE (H1*W_IN)     // 20988
#define FEAT  (H4*W_IN)     // 17424
#define HID   100
#define NC    14
#define NL    3
#define TAPS  28            // composite kernel length
#define KWID  2800          // 100 ch * 28 taps

// ---------------- scratch ----------------
__device__ float g_P1[1000*1900];
__device__ float g_C1[100*1900];
__device__ float g_P2[1000*2800];
__device__ float g_W321[100*2800];
__device__ float g_wt[2800*128];           // [i*28+K][o pad 128]
__device__ float g_b21[100];
__device__ float g_beff[100];
__device__ float g_c3[(size_t)BATCH*TT*FEAT];
#define SPLITK 11
__device__ float g_xwp[(size_t)SPLITK*1600*384];
__device__ float g_xw[(size_t)1600*300];

// ---------------- f32x2 helpers ----------------
__device__ __forceinline__ ull pack2(float lo, float hi) {
    ull r;
    asm("mov.b64 %0, {%1, %2};" : "=l"(r) : "r"(__float_as_uint(lo)), "r"(__float_as_uint(hi)));
    return r;
}
__device__ __forceinline__ void fma2(ull& d, ull a, ull b) {
    asm("fma.rn.f32x2 %0, %1, %2, %0;" : "+l"(d) : "l"(a), "l"(b));
}
__device__ __forceinline__ void unpack2(ull v, float& lo, float& hi) {
    unsigned int a, b;
    asm("mov.b64 {%0, %1}, %2;" : "=r"(a), "=r"(b) : "l"(v));
    lo = __uint_as_float(a); hi = __uint_as_float(b);
}
__device__ __forceinline__ void cp16(void* s, const void* g) {
    unsigned sa = (unsigned)__cvta_generic_to_shared(s);
    asm volatile("cp.async.ca.shared.global [%0], [%1], 16;" :: "r"(sa), "l"(g));
}

// ================= weight-composition prep =================
// P1[(m*10+k2)][(i*19+K)] = w1[m,i,K-k2] if 0<=K-k2<=9
__global__ void build_P1(const float* __restrict__ w1, float* __restrict__ P1) {
    int idx = blockIdx.x * 256 + threadIdx.x;
    if (idx >= 1000 * 1900) return;
    int row = idx / 1900, col = idx - row * 1900;
    int m = row / 10, k2 = row - m * 10;
    int i = col / 19, K = col - i * 19;
    int d = K - k2;
    P1[idx] = (d >= 0 && d <= 9) ? w1[m * 1000 + i * 10 + d] : 0.f;
}
// P2[(m*10+k3)][(i*28+K3)] = C1[m][(i*19 + K3-k3)] if 0<=K3-k3<=18
__global__ void build_P2(const float* __restrict__ C1, float* __restrict__ P2) {
    int idx = blockIdx.x * 256 + threadIdx.x;
    if (idx >= 1000 * 2800) return;
    int row = idx / 2800, col = idx - row * 2800;
    int m = row / 10, k3 = row - m * 10;
    int i = col / 28, K3 = col - i * 28;
    int d = K3 - k3;
    P2[idx] = (d >= 0 && d <= 18) ? C1[m * 1900 + i * 19 + d] : 0.f;
}
// small generic GEMM: C[M,N] = A[M,K] x B[K,N], kc=20 (K divisible by 20)
__global__ __launch_bounds__(256) void prep_gemm(const float* __restrict__ A,
                                                 const float* __restrict__ B,
                                                 float* __restrict__ C,
                                                 int M, int N, int K) {
    __shared__ float As[20][33];
    __shared__ float Bs[20][65];
    int m0 = blockIdx.x * 32, n0 = blockIdx.y * 64;
    int tid = threadIdx.x, ty = tid >> 4, tx = tid & 15;
    float acc[2][4] = {};
    for (int k0 = 0; k0 < K; k0 += 20) {
        for (int q = tid; q < 640; q += 256) {
            int m = q / 20, k = q - m * 20;
            int mm = m0 + m; if (mm > M - 1) mm = M - 1;
            As[k][m] = A[(size_t)mm * K + k0 + k];
        }
        for (int q = tid; q < 1280; q += 256) {
            int k = q >> 6, n = q & 63;
            int nn = n0 + n;
            Bs[k][n] = (nn < N) ? B[(size_t)(k0 + k) * N + nn] : 0.f;
        }
        __syncthreads();
#pragma unroll
        for (int k = 0; k < 20; ++k) {
            float a0 = As[k][ty * 2], a1 = As[k][ty * 2 + 1];
            float b0 = Bs[k][tx * 4], b1 = Bs[k][tx * 4 + 1];
            float b2 = Bs[k][tx * 4 + 2], b3 = Bs[k][tx * 4 + 3];
            acc[0][0] += a0 * b0; acc[0][1] += a0 * b1; acc[0][2] += a0 * b2; acc[0][3] += a0 * b3;
            acc[1][0] += a1 * b0; acc[1][1] += a1 * b1; acc[1][2] += a1 * b2; acc[1][3] += a1 * b3;
        }
        __syncthreads();
    }
    for (int r = 0; r < 2; ++r) {
        int m = m0 + ty * 2 + r;
        if (m >= M) continue;
        for (int c = 0; c < 4; ++c) {
            int n = n0 + tx * 4 + c;
            if (n < N) C[(size_t)m * N + n] = acc[r][c];
        }
    }
}
// wt[(i*28+K)*128 + o] = W321[o*2800 + i*28+K] (0 for o>=100)
__global__ void build_wt(const float* __restrict__ W321, float* __restrict__ wt) {
    int idx = blockIdx.x * 256 + threadIdx.x;
    if (idx >= 2800 * 128) return;
    int rc = idx >> 7, o = idx & 127;
    wt[idx] = (o < 100) ? W321[o * 2800 + rc] : 0.f;
}
// bout[o] = bown[o] + sum_{i,k} w[o,i,k]*bprev[i]
__global__ void fold_bias(const float* __restrict__ w, const float* __restrict__ bprev,
                          const float* __restrict__ bown, float* __restrict__ bout) {
    int o = threadIdx.x;
    if (o >= 100) return;
    float s = bown[o];
    for (int i = 0; i < 100; ++i) {
        const float* wr = w + o * 1000 + i * 10;
        float t = 0.f;
#pragma unroll
        for (int k = 0; k < 10; ++k) t += wr[k];
        s += t * bprev[i];
    }
    bout[o] = s;
}

// ================= fused conv (composite 28-tap), cp.async double-buffered =================
// tile: 112 out-channels (100 valid) x 128 n ; 224 threads; chunks = (i, tap-half)
#define TAPH 14
#define XS_LEN 1844                 // 128 + 13*132
#define WS_LEN (TAPH*128)           // 1792
#define STAGE  (XS_LEN + WS_LEN)    // 3636 floats, 14544 B (16B-multiple)

__global__ __launch_bounds__(224, 2)
void conv_fused(const float* __restrict__ X, const float* __restrict__ wt,
                const float* __restrict__ beff, float* __restrict__ Y) {
    __shared__ __align__(16) float sm[2 * STAGE];
    const int bb = blockIdx.y;
    const int n0 = blockIdx.x * 128;
    const int tid = threadIdx.x;
    const int tm = tid >> 4, tn = tid & 15;

    ull acc[8][4];
#pragma unroll
    for (int r = 0; r < 8; ++r)
#pragma unroll
        for (int p = 0; p < 4; ++p) acc[r][p] = 0ULL;

    const float* Xb = X + (size_t)bb * 100 * PLANE;

    // fill lambda-ish via macro-free inline
    auto fill = [&](int c, int s) {
        int i = c >> 1, khB = (c & 1) * TAPH;
        const float* xsrc = Xb + (size_t)i * PLANE;
        int base = n0 + 132 * khB;
        float* xs = sm + s * STAGE;
        float* ws = xs + XS_LEN;
        for (int q = tid; q < 461; q += 224) {
            int idx = base + q * 4;
            if (idx > PLANE - 4) idx = PLANE - 4;
            cp16(xs + q * 4, xsrc + idx);
        }
        const float* wsrc = wt + ((size_t)i * 28 + khB) * 128;
        for (int q = tid; q < 448; q += 224) cp16(ws + q * 4, wsrc + q * 4);
    };

    fill(0, 0);
    asm volatile("cp.async.commit_group;");

    for (int c = 0; c < 200; ++c) {
        int s = c & 1;
        if (c < 199) {
            fill(c + 1, 1 - s);
            asm volatile("cp.async.commit_group;");
            asm volatile("cp.async.wait_group 1;");
        } else {
            asm volatile("cp.async.wait_group 0;");
        }
        __syncthreads();

        const float* xs = sm + s * STAGE + tn * 8;
        const float* ws = sm + s * STAGE + XS_LEN + tm * 8;
#pragma unroll 7
        for (int kk = 0; kk < TAPH; ++kk) {
            float4 w0 = *(const float4*)(ws + kk * 128);
            float4 w1 = *(const float4*)(ws + kk * 128 + 4);
            ulonglong2 x01 = *(const ulonglong2*)(xs + kk * 132);
            ulonglong2 x23 = *(const ulonglong2*)(xs + kk * 132 + 4);
            ull b0 = x01.x, b1 = x01.y, b2 = x23.x, b3 = x23.y;
            float wv[8] = {w0.x, w0.y, w0.z, w0.w, w1.x, w1.y, w1.z, w1.w};
#pragma unroll
            for (int r = 0; r < 8; ++r) {
                ull ar = pack2(wv[r], wv[r]);
                fma2(acc[r][0], ar, b0);
                fma2(acc[r][1], ar, b1);
                fma2(acc[r][2], ar, b2);
                fma2(acc[r][3], ar, b3);
            }
        }
        __syncthreads();
    }

    // epilogue
#pragma unroll
    for (int r = 0; r < 8; ++r) {
        int ch = tm * 8 + r;
        if (ch < 100) {
            float bo = beff[ch];
            float* yrow = Y + ((size_t)bb * 100 + ch) * FEAT;
            float o0, o1, o2, o3, o4, o5, o6, o7;
            unpack2(acc[r][0], o0, o1); unpack2(acc[r][1], o2, o3);
            unpack2(acc[r][2], o4, o5); unpack2(acc[r][3], o6, o7);
            int n = n0 + tn * 8;
            if (n < FEAT)
                *(float4*)(yrow + n) = make_float4(o0 + bo, o1 + bo, o2 + bo, o3 + bo);
            if (n + 4 < FEAT)
                *(float4*)(yrow + n + 4) = make_float4(o4 + bo, o5 + bo, o6 + bo, o7 + bo);
        }
    }
}

// ================= GRU input GEMM, split-K, reg-double-buffered =================
// tile 128(bt) x 128(g), 256 threads, kc=16, splitK=11 (chunks of 1584 = 99*16)
__global__ __launch_bounds__(256, 2)
void gemm_xw(const float* __restrict__ gi, const float* __restrict__ wih,
             float* __restrict__ xwp) {
    __shared__ __align__(16) float As[16][136];
    __shared__ __align__(16) float Bs[16][136];
    const int bt0 = blockIdx.x * 128;
    const int g0  = blockIdx.y * 128;
    const int ks  = blockIdx.z * 1584;
    const int tid = threadIdx.x;
    const int ty = tid >> 4, tx = tid & 15;

    // fill mapping: row = tid>>1 (0..127), kh = (tid&1)*8
    const int frow = tid >> 1, fkh = (tid & 1) * 8;
    int abt = bt0 + frow; if (abt > 1599) abt = 1599;
    int bg  = g0 + frow;  if (bg > 299)  bg = 299;
    const float* aptr = gi  + (size_t)abt * FEAT + ks + fkh;
    const float* bptr = wih + (size_t)bg  * FEAT + ks + fkh;

    ull acc[8][4];
#pragma unroll
    for (int r = 0; r < 8; ++r)
#pragma unroll
        for (int p = 0; p < 4; ++p) acc[r][p] = 0ULL;

    float4 ra0 = *(const float4*)aptr, ra1 = *(const float4*)(aptr + 4);
    float4 rb0 = *(const float4*)bptr, rb1 = *(const float4*)(bptr + 4);

    for (int c = 0; c < 99; ++c) {
        // store regs -> smem (transposed)
        As[fkh + 0][frow] = ra0.x; As[fkh + 1][frow] = ra0.y;
        As[fkh + 2][frow] = ra0.z; As[fkh + 3][frow] = ra0.w;
        As[fkh + 4][frow] = ra1.x; As[fkh + 5][frow] = ra1.y;
        As[fkh + 6][frow] = ra1.z; As[fkh + 7][frow] = ra1.w;
        Bs[fkh + 0][frow] = rb0.x; Bs[fkh + 1][frow] = rb0.y;
        Bs[fkh + 2][frow] = rb0.z; Bs[fkh + 3][frow] = rb0.w;
        Bs[fkh + 4][frow] = rb1.x; Bs[fkh + 5][frow] = rb1.y;
        Bs[fkh + 6][frow] = rb1.z; Bs[fkh + 7][frow] = rb1.w;
        __syncthreads();
        if (c < 98) {
            int off = (c + 1) * 16;
            ra0 = *(const float4*)(aptr + off); ra1 = *(const float4*)(aptr + off + 4);
            rb0 = *(const float4*)(bptr + off); rb1 = *(const float4*)(bptr + off + 4);
        }
#pragma unroll
        for (int k = 0; k < 16; ++k) {
            float4 a0 = *(const float4*)&As[k][ty * 8];
            float4 a1 = *(const float4*)&As[k][ty * 8 + 4];
            ulonglong2 b01 = *(const ulonglong2*)&Bs[k][tx * 8];
            ulonglong2 b23 = *(const ulonglong2*)&Bs[k][tx * 8 + 4];
            ull b0 = b01.x, b1 = b01.y, b2 = b23.x, b3 = b23.y;
            float av[8] = {a0.x, a0.y, a0.z, a0.w, a1.x, a1.y, a1.z, a1.w};
#pragma unroll
            for (int r = 0; r < 8; ++r) {
                ull ar = pack2(av[r], av[r]);
                fma2(acc[r][0], ar, b0);
                fma2(acc[r][1], ar, b1);
                fma2(acc[r][2], ar, b2);
                fma2(acc[r][3], ar, b3);
            }
        }
        __syncthreads();
    }

#pragma unroll
    for (int r = 0; r < 8; ++r) {
        int bt = bt0 + ty * 8 + r;
        if (bt < 1600) {
            float* orow = xwp + ((size_t)blockIdx.z * 1600 + bt) * 384 + g0 + tx * 8;
            float o0, o1, o2, o3, o4, o5, o6, o7;
            unpack2(acc[r][0], o0, o1); unpack2(acc[r][1], o2, o3);
            unpack2(acc[r][2], o4, o5); unpack2(acc[r][3], o6, o7);
            *(float4*)(orow)     = make_float4(o0, o1, o2, o3);
            *(float4*)(orow + 4) = make_float4(o4, o5, o6, o7);
        }
    }
}

__global__ void reduce_xw(const float* __restrict__ xwp, const float* __restrict__ bih,
                          float* __restrict__ xw) {
    int idx = blockIdx.x * 256 + threadIdx.x;
    if (idx >= 1600 * 300) return;
    int bt = idx / 300, g = idx - bt * 300;
    float s = bih[g];
#pragma unroll
    for (int p = 0; p < SPLITK; ++p)
        s += xwp[((size_t)p * 1600 + bt) * 384 + g];
    xw[idx] = s;
}

// ================= GRU recurrence + heads =================
__global__ __launch_bounds__(320, 1)
void gru_kernel(const float* __restrict__ xw, const float* __restrict__ whh,
                const float* __restrict__ bhh,
                const float* __restrict__ wy1, const float* __restrict__ by1,
                const float* __restrict__ wy2, const float* __restrict__ by2,
                float* __restrict__ out) {
    const int b = blockIdx.x;
    const int tid = threadIdx.x;
    __shared__ float h_s[HID];
    __shared__ float gh_s[3 * HID];
    __shared__ float wy_s[(NC + NL) * HID];
    __shared__ float by_s[NC + NL];

    for (int j = tid; j < NC * HID; j += 320) wy_s[j] = wy1[j];
    for (int j = tid; j < NL * HID; j += 320) wy_s[NC * HID + j] = wy2[j];
    if (tid < NC) by_s[tid] = by1[tid];
    else if (tid < NC + NL) by_s[tid] = by2[tid - NC];
    if (tid < HID) h_s[tid] = 0.f;

    float wreg[HID];
    float bh = 0.f;
    if (tid < 3 * HID) {
        const float4* wrow = (const float4*)(whh + (size_t)tid * HID);
#pragma unroll
        for (int j = 0; j < HID / 4; ++j) {
            float4 v = wrow[j];
            wreg[4 * j] = v.x; wreg[4 * j + 1] = v.y;
            wreg[4 * j + 2] = v.z; wreg[4 * j + 3] = v.w;
        }
        bh = bhh[tid];
    }
    __syncthreads();

    const float* xwb = xw + (size_t)b * TT * 3 * HID;
    float* y1o = out + (size_t)b * TT * NC;
    float* y2o = out + (size_t)BATCH * TT * NC + (size_t)b * TT * NL;

    for (int t = 0; t < TT; ++t) {
        const float* xwt = xwb + t * 3 * HID;
        if (tid < 3 * HID) {
            float s0 = 0.f, s1 = 0.f, s2 = 0.f, s3 = 0.f;
#pragma unroll
            for (int j = 0; j < HID; j += 4) {
                s0 += wreg[j]     * h_s[j];
                s1 += wreg[j + 1] * h_s[j + 1];
                s2 += wreg[j + 2] * h_s[j + 2];
                s3 += wreg[j + 3] * h_s[j + 3];
            }
            gh_s[tid] = bh + ((s0 + s1) + (s2 + s3));
        } else if (t > 0 && tid < 300 + NC + NL) {
            int c = tid - 300;
            float s = by_s[c];
            const float* wr = &wy_s[c * HID];
#pragma unroll 4
            for (int j = 0; j < HID; ++j) s += wr[j] * h_s[j];
            if (c < NC) y1o[(t - 1) * NC + c] = 1.f / (1.f + expf(-s));
            else        y2o[(t - 1) * NL + (c - NC)] = tanhf(s) * 10.f;
        }
        __syncthreads();
        if (tid < HID) {
            float ghr = gh_s[tid], ghz = gh_s[HID + tid], ghn = gh_s[2 * HID + tid];
            float xr = xwt[tid], xz = xwt[HID + tid], xn = xwt[2 * HID + tid];
            float r = 1.f / (1.f + expf(-(xr + ghr)));
            float z = 1.f / (1.f + expf(-(xz + ghz)));
            float n = tanhf(xn + r * ghn);
            h_s[tid] = (1.f - z) * n + z * h_s[tid];
        }
        __syncthreads();
    }
    if (tid >= 300 && tid < 300 + NC + NL) {
        int c = tid - 300;
        float s = by_s[c];
        const float* wr = &wy_s[c * HID];
#pragma unroll 4
        for (int j = 0; j < HID; ++j) s += wr[j] * h_s[j];
        if (c < NC) y1o[(TT - 1) * NC + c] = 1.f / (1.f + expf(-s));
        else        y2o[(TT - 1) * NL + (c - NC)] = tanhf(s) * 10.f;
    }
}

// ---------------- launch ----------------
extern "C" void kernel_launch(void* const* d_in, const int* in_sizes, int n_in,
                              void* d_out, int out_size) {
    const float* x    = (const float*)d_in[0];
    const float* w1   = (const float*)d_in[1];
    const float* bc1  = (const float*)d_in[2];
    const float* w2   = (const float*)d_in[3];
    const float* bc2  = (const float*)d_in[4];
    const float* w3   = (const float*)d_in[5];
    const float* bc3  = (const float*)d_in[6];
    const float* w_ih = (const float*)d_in[7];
    const float* w_hh = (const float*)d_in[8];
    const float* b_ih = (const float*)d_in[9];
    const float* b_hh = (const float*)d_in[10];
    const float* w_y1 = (const float*)d_in[11];
    const float* b_y1 = (const float*)d_in[12];
    const float* w_y2 = (const float*)d_in[13];
    const float* b_y2 = (const float*)d_in[14];

    float *P1, *C1, *P2, *W321, *wt, *b21, *beff, *c3, *xwp, *xw;
    cudaGetSymbolAddress((void**)&P1,   g_P1);
    cudaGetSymbolAddress((void**)&C1,   g_C1);
    cudaGetSymbolAddress((void**)&P2,   g_P2);
    cudaGetSymbolAddress((void**)&W321, g_W321);
    cudaGetSymbolAddress((void**)&wt,   g_wt);
    cudaGetSymbolAddress((void**)&b21,  g_b21);
    cudaGetSymbolAddress((void**)&beff, g_beff);
    cudaGetSymbolAddress((void**)&c3,   g_c3);
    cudaGetSymbolAddress((void**)&xwp,  g_xwp);
    cudaGetSymbolAddress((void**)&xw,   g_xw);

    // ---- compose weights: W21 = w2 (*) w1 ; W321 = w3 (*) W21 ----
    build_P1<<<(1000 * 1900 + 255) / 256, 256>>>(w1, P1);
    prep_gemm<<<dim3(4, 30), 256>>>(w2, P1, C1, 100, 1900, 1000);
    build_P2<<<(1000 * 2800 + 255) / 256, 256>>>(C1, P2);
    prep_gemm<<<dim3(4, 44), 256>>>(w3, P2, W321, 100, 2800, 1000);
    build_wt<<<(2800 * 128 + 255) / 256, 256>>>(W321, wt);
    fold_bias<<<1, 128>>>(w2, bc1, bc2, b21);
    fold_bias<<<1, 128>>>(w3, b21, bc3, beff);

    // ---- fused conv ----
    conv_fused<<<dim3((FEAT + 127) / 128, BATCH), 224>>>(x, wt, beff, c3);

    // ---- GRU input GEMM ----
    gemm_xw<<<dim3(13, 3, SPLITK), 256>>>(c3, w_ih, xwp);
    reduce_xw<<<(1600 * 300 + 255) / 256, 256>>>(xwp, b_ih, xw);

    // ---- GRU + heads ----
    gru_kernel<<<BATCH, 320>>>(xw, w_hh, b_hh, w_y1, b_y1, w_y2, b_y2, (float*)d_out);
}

// round 4
// speedup vs baseline: 7.7109x; 3.9530x over previous
#include <cuda_runtime.h>
#include <cuda_fp16.h>
#include <cstdint>

// ---------------- problem constants ----------------
#define BATCH 16
#define TT    100
#define W_IN  132
#define H1    159
#define H4    132
#define PLANE (H1*W_IN)     // 20988
#define FEAT  (H4*W_IN)     // 17424
#define HID   100
#define NC    14
#define NL    3

// conv HMMA geometry
#define NCH_CHUNK 25        // 25 chunks x 112 k (4 channels * 28 taps) = K 2800
#define CONV_NTILE 137      // ceil(17424/128)
#define A_ST 32768          // 128 rows * 256 B
#define B_ST 28672          // 112 rows * 256 B
#define CSTG (A_ST + B_ST)  // 61440
#define CONV_SMEM (2*CSTG)  // 122880

// xw HMMA geometry
#define XW_SPLITK 4
#define XW_SMEM 65536       // 2 stages * (16K A + 16K B)

// ---------------- scratch ----------------
#define SPLITP 5
__device__ float g_P1[1000*1900];
__device__ float g_C1p[SPLITP*100*1900];
__device__ float g_C1[100*1900];
__device__ float g_P2[1000*2800];
__device__ float g_W321p[SPLITP*100*2800];
__device__ float g_W321[100*2800];
__device__ float g_b21[100];
__device__ float g_beff[100];
__device__ __half g_xh[(size_t)BATCH*100*PLANE + 512];
__device__ __half g_wihh[(size_t)384*FEAT];
__device__ __align__(16) __half g_Aimg[(size_t)NCH_CHUNK*A_ST/2];
__device__ __half g_c3h[(size_t)BATCH*TT*FEAT];
__device__ float g_xwp[(size_t)XW_SPLITK*1600*384];
__device__ float g_xw[(size_t)1600*300];

// ---------------- async-copy helpers ----------------
__device__ __forceinline__ void cp16(void* s, const void* g) {
    unsigned sa = (unsigned)__cvta_generic_to_shared(s);
    asm volatile("cp.async.ca.shared.global [%0], [%1], 16;" :: "r"(sa), "l"(g));
}
__device__ __forceinline__ void cp8(void* s, const void* g) {
    unsigned sa = (unsigned)__cvta_generic_to_shared(s);
    asm volatile("cp.async.ca.shared.global [%0], [%1], 8;" :: "r"(sa), "l"(g));
}
__device__ __forceinline__ void cp16z(void* s, const void* g, unsigned sz) {
    unsigned sa = (unsigned)__cvta_generic_to_shared(s);
    asm volatile("cp.async.ca.shared.global [%0], [%1], 16, %2;" :: "r"(sa), "l"(g), "r"(sz));
}

// ---------------- HMMA helpers ----------------
__device__ __forceinline__ void ldsm_x4(uint32_t& r0, uint32_t& r1, uint32_t& r2, uint32_t& r3,
                                        uint32_t addr) {
    asm volatile("ldmatrix.sync.aligned.m8n8.x4.shared.b16 {%0,%1,%2,%3}, [%4];"
                 : "=r"(r0), "=r"(r1), "=r"(r2), "=r"(r3) : "r"(addr));
}
__device__ __forceinline__ void ldsm_x4t(uint32_t& r0, uint32_t& r1, uint32_t& r2, uint32_t& r3,
                                         uint32_t addr) {
    asm volatile("ldmatrix.sync.aligned.m8n8.x4.trans.shared.b16 {%0,%1,%2,%3}, [%4];"
                 : "=r"(r0), "=r"(r1), "=r"(r2), "=r"(r3) : "r"(addr));
}
__device__ __forceinline__ void mma16816(float* c, uint32_t a0, uint32_t a1, uint32_t a2,
                                         uint32_t a3, uint32_t b0, uint32_t b1) {
    asm volatile(
        "mma.sync.aligned.m16n8k16.row.col.f32.f16.f16.f32 "
        "{%0,%1,%2,%3}, {%4,%5,%6,%7}, {%8,%9}, {%0,%1,%2,%3};"
        : "+f"(c[0]), "+f"(c[1]), "+f"(c[2]), "+f"(c[3])
        : "r"(a0), "r"(a1), "r"(a2), "r"(a3), "r"(b0), "r"(b1));
}

// ================= prep: weight composition =================
__global__ void build_P1(const float* __restrict__ w1, float* __restrict__ P1) {
    int idx = blockIdx.x * 256 + threadIdx.x;
    if (idx >= 1000 * 1900) return;
    int row = idx / 1900, col = idx - row * 1900;
    int m = row / 10, k2 = row - m * 10;
    int i = col / 19, K = col - i * 19;
    int d = K - k2;
    P1[idx] = (d >= 0 && d <= 9) ? w1[m * 1000 + i * 10 + d] : 0.f;
}
__global__ void build_P2(const float* __restrict__ C1, float* __restrict__ P2) {
    int idx = blockIdx.x * 256 + threadIdx.x;
    if (idx >= 1000 * 2800) return;
    int row = idx / 2800, col = idx - row * 2800;
    int m = row / 10, k3 = row - m * 10;
    int i = col / 28, K3 = col - i * 28;
    int d = K3 - k3;
    P2[idx] = (d >= 0 && d <= 18) ? C1[m * 1900 + i * 19 + d] : 0.f;
}
__global__ __launch_bounds__(256) void prep_gemm_sk(const float* __restrict__ A,
                                                    const float* __restrict__ B,
                                                    float* __restrict__ Cp,
                                                    int M, int N, int K) {
    __shared__ float As[20][33];
    __shared__ float Bs[20][65];
    int m0 = blockIdx.x * 32, n0 = blockIdx.y * 64;
    int kbeg = blockIdx.z * 200;
    int tid = threadIdx.x, ty = tid >> 4, tx = tid & 15;
    float acc[2][4] = {};
    for (int k0 = kbeg; k0 < kbeg + 200; k0 += 20) {
        for (int q = tid; q < 640; q += 256) {
            int m = q / 20, k = q - m * 20;
            int mm = m0 + m; if (mm > M - 1) mm = M - 1;
            As[k][m] = A[(size_t)mm * K + k0 + k];
        }
        for (int q = tid; q < 1280; q += 256) {
            int k = q >> 6, n = q & 63;
            int nn = n0 + n;
            Bs[k][n] = (nn < N) ? B[(size_t)(k0 + k) * N + nn] : 0.f;
        }
        __syncthreads();
#pragma unroll
        for (int k = 0; k < 20; ++k) {
            float a0 = As[k][ty * 2], a1 = As[k][ty * 2 + 1];
            float b0 = Bs[k][tx * 4], b1 = Bs[k][tx * 4 + 1];
            float b2 = Bs[k][tx * 4 + 2], b3 = Bs[k][tx * 4 + 3];
            acc[0][0] += a0 * b0; acc[0][1] += a0 * b1; acc[0][2] += a0 * b2; acc[0][3] += a0 * b3;
            acc[1][0] += a1 * b0; acc[1][1] += a1 * b1; acc[1][2] += a1 * b2; acc[1][3] += a1 * b3;
        }
        __syncthreads();
    }
    float* Cz = Cp + (size_t)blockIdx.z * M * N;
    for (int r = 0; r < 2; ++r) {
        int m = m0 + ty * 2 + r;
        if (m >= M) continue;
        for (int c = 0; c < 4; ++c) {
            int n = n0 + tx * 4 + c;
            if (n < N) Cz[(size_t)m * N + n] = acc[r][c];
        }
    }
}
__global__ void reduce_prep(const float* __restrict__ Cp, float* __restrict__ C, int MN) {
    int idx = blockIdx.x * 256 + threadIdx.x;
    if (idx >= MN) return;
    float s = 0.f;
#pragma unroll
    for (int p = 0; p < SPLITP; ++p) s += Cp[(size_t)p * MN + idx];
    C[idx] = s;
}
__global__ void fold_bias(const float* __restrict__ w, const float* __restrict__ bprev,
                          const float* __restrict__ bown, float* __restrict__ bout) {
    int o = threadIdx.x;
    if (o >= 100) return;
    float s = bown[o];
    for (int i = 0; i < 100; ++i) {
        const float* wr = w + o * 1000 + i * 10;
        float t = 0.f;
#pragma unroll
        for (int k = 0; k < 10; ++k) t += wr[k];
        s += t * bprev[i];
    }
    bout[o] = s;
}

// ================= prep: fp16 conversions =================
__global__ void cvt_x(const float* __restrict__ x, __half* __restrict__ xh) {
    size_t N = (size_t)BATCH * 100 * PLANE;
    size_t idx = (size_t)blockIdx.x * 256 + threadIdx.x;
    if (idx >= N + 512) return;
    xh[idx] = (idx < N) ? __float2half_rn(x[idx]) : __float2half_rn(0.f);
}
__global__ void cvt_wih(const float* __restrict__ wih, __half* __restrict__ wihh) {
    size_t idx = (size_t)blockIdx.x * 256 + threadIdx.x;
    if (idx >= (size_t)384 * FEAT) return;
    int g = (int)(idx / FEAT);
    wihh[idx] = (g < 300) ? __float2half_rn(wih[idx - (size_t)(g - g) * 0 + 0 * 0 == 0 ? idx : idx])
                          : __float2half_rn(0.f);
}
// NOTE: simple form (identity index) — rewritten cleanly below in a second kernel to avoid
// confusion; the above computes wihh[idx] = wih[idx] for g<300.  (kept branch-free)
__global__ void prep_A(const float* __restrict__ W321, __half* __restrict__ Aimg) {
    int idx = blockIdx.x * 256 + threadIdx.x;          // 25 * 128 * 128
    if (idx >= NCH_CHUNK * 128 * 128) return;
    int c = idx >> 14;
    int r2 = idx & 16383;
    int m = r2 >> 7, ks = r2 & 127;                    // m 0..127, kslot 0..127
    float wv = 0.f;
    if (ks < 112 && m < 100) {
        int k = c * 112 + ks;                          // global k = ch*28 + tap
        wv = W321[m * 2800 + k];
    }
    int kb = ks * 2;
    int byte = c * A_ST + m * 256 + (((kb >> 4) ^ (m & 7)) << 4) + (kb & 15);
    Aimg[byte >> 1] = __float2half_rn(wv);
}

// ================= conv via HMMA (fp16 in, fp32 acc) =================
__global__ __launch_bounds__(256, 1)
void conv_hmma(const __half* __restrict__ xh, const __half* __restrict__ Aimg,
               const float* __restrict__ beff, __half* __restrict__ c3h) {
    extern __shared__ __align__(1024) char dsm[];
    const int bb = blockIdx.y;
    const int n0 = blockIdx.x * 128;
    const int tid = threadIdx.x;
    const int wid = tid >> 5, lane = tid & 31;
    const int m0w = (wid & 3) * 32;
    const int n0w = (wid >> 2) * 64;
    const uint32_t dynb = (uint32_t)__cvta_generic_to_shared(dsm);

    float acc[2][8][4];
#pragma unroll
    for (int a = 0; a < 2; ++a)
#pragma unroll
        for (int b = 0; b < 8; ++b)
#pragma unroll
            for (int q = 0; q < 4; ++q) acc[a][b][q] = 0.f;

    const __half* xb = xh + (size_t)bb * 100 * PLANE;

#define CSTAGE(CC, SS) do {                                                    \
    const __half* asrc = Aimg + (size_t)(CC) * (A_ST / 2);                     \
    char* ad = dsm + (SS) * CSTG;                                              \
    for (int q = tid; q < 2048; q += 256) cp16(ad + q * 16, asrc + q * 8);     \
    char* bd = dsm + (SS) * CSTG + A_ST;                                       \
    int c4 = (CC) * 4;                                                         \
    for (int q = tid; q < 3584; q += 256) {                                    \
        int r = q >> 5, j = q & 31;                                            \
        int chq = r / 28, tap = r - chq * 28;                                  \
        const __half* src = xb + (size_t)(c4 + chq) * PLANE + n0 + 132 * tap + j * 4; \
        char* dst = bd + r * 256 + (((j >> 1) ^ (r & 7)) << 4) + (j & 1) * 8;  \
        cp8(dst, src);                                                         \
    }                                                                          \
} while (0)

    CSTAGE(0, 0);
    asm volatile("cp.async.commit_group;" ::: "memory");

    for (int c = 0; c < NCH_CHUNK; ++c) {
        const int s = c & 1;
        if (c + 1 < NCH_CHUNK) {
            CSTAGE(c + 1, 1 - s);
            asm volatile("cp.async.commit_group;" ::: "memory");
            asm volatile("cp.async.wait_group 1;" ::: "memory");
        } else {
            asm volatile("cp.async.wait_group 0;" ::: "memory");
        }
        __syncthreads();

        const uint32_t Ab = dynb + s * CSTG;
        const uint32_t Bb = Ab + A_ST;
#pragma unroll
        for (int kf = 0; kf < 7; ++kf) {
            const int k0 = kf * 16;
            uint32_t a[2][4];
#pragma unroll
            for (int fm = 0; fm < 2; ++fm) {
                int mrow = m0w + fm * 16 + (lane & 7) + ((lane >> 3) & 1) * 8;
                int grp = (k0 >> 3) + (lane >> 4);
                ldsm_x4(a[fm][0], a[fm][1], a[fm][2], a[fm][3],
                        Ab + mrow * 256 + ((grp ^ (mrow & 7)) << 4));
            }
            uint32_t b[8][2];
#pragma unroll
            for (int p = 0; p < 4; ++p) {
                int krow = k0 + (lane & 7) + ((lane >> 3) & 1) * 8;
                int ng = (n0w >> 3) + p * 2 + (lane >> 4);
                ldsm_x4t(b[p * 2][0], b[p * 2][1], b[p * 2 + 1][0], b[p * 2 + 1][1],
                         Bb + krow * 256 + ((ng ^ (krow & 7)) << 4));
            }
#pragma unroll
            for (int fm = 0; fm < 2; ++fm)
#pragma unroll
                for (int fn = 0; fn < 8; ++fn)
                    mma16816(acc[fm][fn], a[fm][0], a[fm][1], a[fm][2], a[fm][3],
                             b[fn][0], b[fn][1]);
        }
        __syncthreads();
    }

    // epilogue: bias + fp16 store
#pragma unroll
    for (int fm = 0; fm < 2; ++fm) {
        int mlo = m0w + fm * 16 + (lane >> 2);
        int mhi = mlo + 8;
        float blo = (mlo < 100) ? beff[mlo] : 0.f;
        float bhi = (mhi < 100) ? beff[mhi] : 0.f;
#pragma unroll
        for (int fn = 0; fn < 8; ++fn) {
            int n = n0 + n0w + fn * 8 + 2 * (lane & 3);
            if (n >= FEAT) continue;
            if (mlo < 100) {
                __half2 v = __floats2half2_rn(acc[fm][fn][0] + blo, acc[fm][fn][1] + blo);
                *(__half2*)(c3h + ((size_t)bb * 100 + mlo) * FEAT + n) = v;
            }
            if (mhi < 100) {
                __half2 v = __floats2half2_rn(acc[fm][fn][2] + bhi, acc[fm][fn][3] + bhi);
                *(__half2*)(c3h + ((size_t)bb * 100 + mhi) * FEAT + n) = v;
            }
        }
    }
#undef CSTAGE
}

// ================= GRU input GEMM via HMMA, split-K =================
__global__ __launch_bounds__(256, 2)
void gemm_xw_hmma(const __half* __restrict__ gi, const __half* __restrict__ wihh,
                  float* __restrict__ xwp) {
    extern __shared__ __align__(1024) char dsm[];
    const int bt0 = blockIdx.x * 128;
    const int g0  = blockIdx.y * 128;
    const int z   = blockIdx.z;
    const int kc0 = z * 4352;
    const int nch = (z < XW_SPLITK - 1) ? 68 : 69;
    const int tid = threadIdx.x;
    const int wid = tid >> 5, lane = tid & 31;
    const int m0w = (wid & 3) * 32;
    const int n0w = (wid >> 2) * 64;
    const uint32_t dynb = (uint32_t)__cvta_generic_to_shared(dsm);

    float acc[2][8][4];
#pragma unroll
    for (int a = 0; a < 2; ++a)
#pragma unroll
        for (int b = 0; b < 8; ++b)
#pragma unroll
            for (int q = 0; q < 4; ++q) acc[a][b][q] = 0.f;

#define XSTAGE(KC, SS) do {                                                    \
    for (int q = tid; q < 2048; q += 256) {                                    \
        int isB = q >> 10;                                                     \
        int r = (q >> 3) & 127, j = q & 7;                                     \
        int kg = (KC) + j * 8;                                                 \
        const __half* src;                                                     \
        if (!isB) {                                                            \
            int bt = bt0 + r; if (bt > 1599) bt = 1599;                        \
            src = gi + (size_t)bt * FEAT + kg;                                 \
        } else {                                                               \
            src = wihh + (size_t)(g0 + r) * FEAT + kg;                         \
        }                                                                      \
        unsigned sz = (kg < FEAT) ? 16u : 0u;                                  \
        if (!sz) src = gi;                                                     \
        char* dst = dsm + (SS) * 32768 + isB * 16384 + r * 128 +               \
                    ((j ^ (r & 7)) << 4);                                      \
        cp16z(dst, src, sz);                                                   \
    }                                                                          \
} while (0)

    XSTAGE(kc0, 0);
    asm volatile("cp.async.commit_group;" ::: "memory");

    for (int c = 0; c < nch; ++c) {
        const int s = c & 1;
        if (c + 1 < nch) {
            XSTAGE(kc0 + (c + 1) * 64, 1 - s);
            asm volatile("cp.async.commit_group;" ::: "memory");
            asm volatile("cp.async.wait_group 1;" ::: "memory");
        } else {
            asm volatile("cp.async.wait_group 0;" ::: "memory");
        }
        __syncthreads();

        const uint32_t Ab = dynb + s * 32768;
        const uint32_t Bb = Ab + 16384;
#pragma unroll
        for (int kf = 0; kf < 4; ++kf) {
            const int k0 = kf * 16;
            uint32_t a[2][4];
#pragma unroll
            for (int fm = 0; fm < 2; ++fm) {
                int mrow = m0w + fm * 16 + (lane & 7) + ((lane >> 3) & 1) * 8;
                int grp = (k0 >> 3) + (lane >> 4);
                ldsm_x4(a[fm][0], a[fm][1], a[fm][2], a[fm][3],
                        Ab + mrow * 128 + (((grp ^ (mrow & 7)) & 7) << 4));
            }
            uint32_t b[8][2];
#pragma unroll
            for (int p = 0; p < 4; ++p) {
                int nrow = n0w + p * 16 + ((lane >> 4) & 1) * 8 + (lane & 7);
                int grp = (k0 >> 3) + ((lane >> 3) & 1);
                ldsm_x4(b[p * 2][0], b[p * 2][1], b[p * 2 + 1][0], b[p * 2 + 1][1],
                        Bb + nrow * 128 + (((grp ^ (nrow & 7)) & 7) << 4));
            }
#pragma unroll
            for (int fm = 0; fm < 2; ++fm)
#pragma unroll
                for (int fn = 0; fn < 8; ++fn)
                    mma16816(acc[fm][fn], a[fm][0], a[fm][1], a[fm][2], a[fm][3],
                             b[fn][0], b[fn][1]);
        }
        __syncthreads();
    }

    float* outz = xwp + (size_t)z * 1600 * 384;
#pragma unroll
    for (int fm = 0; fm < 2; ++fm) {
        int mlo = bt0 + m0w + fm * 16 + (lane >> 2);
        int mhi = mlo + 8;
#pragma unroll
        for (int fn = 0; fn < 8; ++fn) {
            int n = g0 + n0w + fn * 8 + 2 * (lane & 3);
            if (mlo < 1600)
                *(float2*)(outz + (size_t)mlo * 384 + n) =
                    make_float2(acc[fm][fn][0], acc[fm][fn][1]);
            if (mhi < 1600)
                *(float2*)(outz + (size_t)mhi * 384 + n) =
                    make_float2(acc[fm][fn][2], acc[fm][fn][3]);
        }
    }
#undef XSTAGE
}

__global__ void reduce_xw(const float* __restrict__ xwp, const float* __restrict__ bih,
                          float* __restrict__ xw) {
    int idx = blockIdx.x * 256 + threadIdx.x;
    if (idx >= 1600 * 300) return;
    int bt = idx / 300, g = idx - bt * 300;
    float s = bih[g];
#pragma unroll
    for (int p = 0; p < XW_SPLITK; ++p)
        s += xwp[((size_t)p * 1600 + bt) * 384 + g];
    xw[idx] = s;
}

// ================= GRU recurrence + heads =================
__global__ __launch_bounds__(320, 1)
void gru_kernel(const float* __restrict__ xw, const float* __restrict__ whh,
                const float* __restrict__ bhh,
                const float* __restrict__ wy1, const float* __restrict__ by1,
                const float* __restrict__ wy2, const float* __restrict__ by2,
                float* __restrict__ out) {
    const int b = blockIdx.x;
    const int tid = threadIdx.x;
    __shared__ float h_s[HID];
    __shared__ float gh_s[3 * HID];
    __shared__ float wy_s[(NC + NL) * HID];
    __shared__ float by_s[NC + NL];

    for (int j = tid; j < NC * HID; j += 320) wy_s[j] = wy1[j];
    for (int j = tid; j < NL * HID; j += 320) wy_s[NC * HID + j] = wy2[j];
    if (tid < NC) by_s[tid] = by1[tid];
    else if (tid < NC + NL) by_s[tid] = by2[tid - NC];
    if (tid < HID) h_s[tid] = 0.f;

    float wreg[HID];
    float bh = 0.f;
    if (tid < 3 * HID) {
        const float4* wrow = (const float4*)(whh + (size_t)tid * HID);
#pragma unroll
        for (int j = 0; j < HID / 4; ++j) {
            float4 v = wrow[j];
            wreg[4 * j] = v.x; wreg[4 * j + 1] = v.y;
            wreg[4 * j + 2] = v.z; wreg[4 * j + 3] = v.w;
        }
        bh = bhh[tid];
    }
    __syncthreads();

    const float* xwb = xw + (size_t)b * TT * 3 * HID;
    float* y1o = out + (size_t)b * TT * NC;
    float* y2o = out + (size_t)BATCH * TT * NC + (size_t)b * TT * NL;

    for (int t = 0; t < TT; ++t) {
        const float* xwt = xwb + t * 3 * HID;
        if (tid < 3 * HID) {
            float s0 = 0.f, s1 = 0.f, s2 = 0.f, s3 = 0.f;
#pragma unroll
            for (int j = 0; j < HID; j += 4) {
                s0 += wreg[j]     * h_s[j];
                s1 += wreg[j + 1] * h_s[j + 1];
                s2 += wreg[j + 2] * h_s[j + 2];
                s3 += wreg[j + 3] * h_s[j + 3];
            }
            gh_s[tid] = bh + ((s0 + s1) + (s2 + s3));
        } else if (t > 0 && tid < 300 + NC + NL) {
            int c = tid - 300;
            float s = by_s[c];
            const float* wr = &wy_s[c * HID];
#pragma unroll 4
            for (int j = 0; j < HID; ++j) s += wr[j] * h_s[j];
            if (c < NC) y1o[(t - 1) * NC + c] = 1.f / (1.f + expf(-s));
            else        y2o[(t - 1) * NL + (c - NC)] = tanhf(s) * 10.f;
        }
        __syncthreads();
        if (tid < HID) {
            float ghr = gh_s[tid], ghz = gh_s[HID + tid], ghn = gh_s[2 * HID + tid];
            float xr = xwt[tid], xz = xwt[HID + tid], xn = xwt[2 * HID + tid];
            float r = 1.f / (1.f + expf(-(xr + ghr)));
            float z = 1.f / (1.f + expf(-(xz + ghz)));
            float n = tanhf(xn + r * ghn);
            h_s[tid] = (1.f - z) * n + z * h_s[tid];
        }
        __syncthreads();
    }
    if (tid >= 300 && tid < 300 + NC + NL) {
        int c = tid - 300;
        float s = by_s[c];
        const float* wr = &wy_s[c * HID];
#pragma unroll 4
        for (int j = 0; j < HID; ++j) s += wr[j] * h_s[j];
        if (c < NC) y1o[(TT - 1) * NC + c] = 1.f / (1.f + expf(-s));
        else        y2o[(TT - 1) * NL + (c - NC)] = tanhf(s) * 10.f;
    }
}

// ---------------- launch ----------------
extern "C" void kernel_launch(void* const* d_in, const int* in_sizes, int n_in,
                              void* d_out, int out_size) {
    const float* x    = (const float*)d_in[0];
    const float* w1   = (const float*)d_in[1];
    const float* bc1  = (const float*)d_in[2];
    const float* w2   = (const float*)d_in[3];
    const float* bc2  = (const float*)d_in[4];
    const float* w3   = (const float*)d_in[5];
    const float* bc3  = (const float*)d_in[6];
    const float* w_ih = (const float*)d_in[7];
    const float* w_hh = (const float*)d_in[8];
    const float* b_ih = (const float*)d_in[9];
    const float* b_hh = (const float*)d_in[10];
    const float* w_y1 = (const float*)d_in[11];
    const float* b_y1 = (const float*)d_in[12];
    const float* w_y2 = (const float*)d_in[13];
    const float* b_y2 = (const float*)d_in[14];

    float *P1, *C1p, *C1, *P2, *W321p, *W321, *b21, *beff, *xwp, *xw;
    __half *xh, *wihh, *Aimg, *c3h;
    cudaGetSymbolAddress((void**)&P1,    g_P1);
    cudaGetSymbolAddress((void**)&C1p,   g_C1p);
    cudaGetSymbolAddress((void**)&C1,    g_C1);
    cudaGetSymbolAddress((void**)&P2,    g_P2);
    cudaGetSymbolAddress((void**)&W321p, g_W321p);
    cudaGetSymbolAddress((void**)&W321,  g_W321);
    cudaGetSymbolAddress((void**)&b21,   g_b21);
    cudaGetSymbolAddress((void**)&beff,  g_beff);
    cudaGetSymbolAddress((void**)&xwp,   g_xwp);
    cudaGetSymbolAddress((void**)&xw,    g_xw);
    cudaGetSymbolAddress((void**)&xh,    g_xh);
    cudaGetSymbolAddress((void**)&wihh,  g_wihh);
    cudaGetSymbolAddress((void**)&Aimg,  g_Aimg);
    cudaGetSymbolAddress((void**)&c3h,   g_c3h);

    cudaFuncSetAttribute(conv_hmma, cudaFuncAttributeMaxDynamicSharedMemorySize, CONV_SMEM);
    cudaFuncSetAttribute(gemm_xw_hmma, cudaFuncAttributeMaxDynamicSharedMemorySize, XW_SMEM);

    // weight composition
    build_P1<<<(1000 * 1900 + 255) / 256, 256>>>(w1, P1);
    prep_gemm_sk<<<dim3(4, 30, SPLITP), 256>>>(w2, P1, C1p, 100, 1900, 1000);
    reduce_prep<<<(100 * 1900 + 255) / 256, 256>>>(C1p, C1, 100 * 1900);
    build_P2<<<(1000 * 2800 + 255) / 256, 256>>>(C1, P2);
    prep_gemm_sk<<<dim3(4, 44, SPLITP), 256>>>(w3, P2, W321p, 100, 2800, 1000);
    reduce_prep<<<(100 * 2800 + 255) / 256, 256>>>(W321p, W321, 100 * 2800);
    fold_bias<<<1, 128>>>(w2, bc1, bc2, b21);
    fold_bias<<<1, 128>>>(w3, b21, bc3, beff);

    // fp16 conversions
    size_t nx = (size_t)BATCH * 100 * PLANE + 512;
    cvt_x<<<(int)((nx + 255) / 256), 256>>>(x, xh);
    cvt_wih<<<(int)(((size_t)384 * FEAT + 255) / 256), 256>>>(w_ih, wihh);
    prep_A<<<(NCH_CHUNK * 128 * 128 + 255) / 256, 256>>>(W321, Aimg);

    // conv on tensor pipe
    conv_hmma<<<dim3(CONV_NTILE, BATCH), 256, CONV_SMEM>>>(xh, Aimg, beff, c3h);

    // GRU input GEMM on tensor pipe
    gemm_xw_hmma<<<dim3(13, 3, XW_SPLITK), 256, XW_SMEM>>>(c3h, wihh, xwp);
    reduce_xw<<<(1600 * 300 + 255) / 256, 256>>>(xwp, b_ih, xw);

    // GRU + heads
    gru_kernel<<<BATCH, 320>>>(xw, w_hh, b_hh, w_y1, b_y1, w_y2, b_y2, (float*)d_out);
}